// round 2
// baseline (speedup 1.0000x reference)
#include <cuda_runtime.h>

// WaveletLayer: z = leaky_relu(idwt_db2(cA, w0 * cD)) where (cA, cD) = dwt_db2(x)
// x: (B=65536, D=512) fp32, weight: (2, 257) fp32 (row 0 used), out: (B, D) fp32.
// Pure HBM-streaming fused kernel: 1 read + 1 write of the tensor.

#define D_LEN 512
#define L_LEN 257          // D/2 + 1
#define ROWS_PER_BLOCK 2
#define LANES 128          // D / 4 (one float4 per lane)
#define THREADS (ROWS_PER_BLOCK * LANES)

__global__ __launch_bounds__(THREADS)
void wavelet_fused_kernel(const float* __restrict__ x,
                          const float* __restrict__ w,   // weight[0], 257 floats
                          float* __restrict__ out,
                          int B)
{
    // db2 filter banks (pywt), fp32
    const float dl0 = -0.12940952255092145f, dl1 = 0.22414386804185735f,
                dl2 =  0.836516303737469f,   dl3 = 0.48296291314469025f;
    const float dh0 = -0.48296291314469025f, dh1 = 0.836516303737469f,
                dh2 = -0.22414386804185735f, dh3 = -0.12940952255092145f;
    const float rl0 =  0.48296291314469025f, rl1 = 0.836516303737469f,
                rl2 =  0.22414386804185735f, rl3 = -0.12940952255092145f;
    const float rh0 = -0.12940952255092145f, rh1 = -0.22414386804185735f,
                rh2 =  0.836516303737469f,   rh3 = -0.48296291314469025f;

    __shared__ float s_x [ROWS_PER_BLOCK][D_LEN];
    __shared__ float s_cA[ROWS_PER_BLOCK][L_LEN + 3];   // +pad
    __shared__ float s_cD[ROWS_PER_BLOCK][L_LEN + 3];

    const int tid  = threadIdx.x;
    const int r    = tid >> 7;          // row slot within block
    const int lane = tid & 127;         // 0..127
    const long long row = (long long)blockIdx.x * ROWS_PER_BLOCK + r;
    if (row >= B) return;

    const long long base = row * (long long)D_LEN;

    // ---- load: one float4 per lane (coalesced 128-bit) ----
    const float4 v = reinterpret_cast<const float4*>(x + base)[lane];
    reinterpret_cast<float4*>(s_x[r])[lane] = v;
    __syncthreads();

    // ---- DWT: each lane computes cA/cD at i0 = 2*lane and i1 = 2*lane+1 ----
    const int i0 = 2 * lane;
    const int i1 = i0 + 1;

    // interior: cA[i] = dl0*x[2i+1] + dl1*x[2i] + dl2*x[2i-1] + dl3*x[2i-2]
    // i0 = 2*lane needs x[4l-2], x[4l-1] (halo); symmetric mirror at lane 0:
    //   x[-1] -> x[0] (= v.x), x[-2] -> x[1] (= v.y)
    float xm2, xm1;
    if (lane == 0) { xm2 = v.y; xm1 = v.x; }
    else           { xm2 = s_x[r][4 * lane - 2]; xm1 = s_x[r][4 * lane - 1]; }

    const float a0 = dl0 * v.y + dl1 * v.x + dl2 * xm1 + dl3 * xm2;
    const float d0 = dh0 * v.y + dh1 * v.x + dh2 * xm1 + dh3 * xm2;
    const float a1 = dl0 * v.w + dl1 * v.z + dl2 * v.y + dl3 * v.x;
    const float d1 = dh0 * v.w + dh1 * v.z + dh2 * v.y + dh3 * v.x;

    // cD scaled by weight[0][i] (weight is identical for all rows -> L1 hit)
    s_cA[r][i0] = a0;
    s_cA[r][i1] = a1;
    s_cD[r][i0] = d0 * __ldg(&w[i0]);
    s_cD[r][i1] = d1 * __ldg(&w[i1]);

    if (lane == 127) {
        // i = 256: mirror tail  x[512]->x[511], x[513]->x[510]
        // cA[256] = dl0*x[510] + dl1*x[511] + dl2*x[511] + dl3*x[510]
        // lane 127 holds x[508..511] = v.{x,y,z,w} -> x510=v.z, x511=v.w
        const float aL = dl0 * v.z + dl1 * v.w + dl2 * v.w + dl3 * v.z;
        const float dL = dh0 * v.z + dh1 * v.w + dh2 * v.w + dh3 * v.z;
        s_cA[r][256] = aL;
        s_cD[r][256] = dL * __ldg(&w[256]);
    }
    __syncthreads();

    // ---- iDWT + leaky_relu: each lane emits t = 4*lane .. 4*lane+3 ----
    const float A0 = s_cA[r][i0], A1 = s_cA[r][i1], A2 = s_cA[r][i0 + 2];
    const float E0 = s_cD[r][i0], E1 = s_cD[r][i1], E2 = s_cD[r][i0 + 2];

    float4 z;
    z.x = rl2 * A0 + rl0 * A1 + rh2 * E0 + rh0 * E1;   // t even, i = i0
    z.y = rl3 * A0 + rl1 * A1 + rh3 * E0 + rh1 * E1;   // t odd,  i = i0
    z.z = rl2 * A1 + rl0 * A2 + rh2 * E1 + rh0 * E2;   // t even, i = i1
    z.w = rl3 * A1 + rl1 * A2 + rh3 * E1 + rh1 * E2;   // t odd,  i = i1

    z.x = (z.x > 0.0f) ? z.x : 0.01f * z.x;
    z.y = (z.y > 0.0f) ? z.y : 0.01f * z.y;
    z.z = (z.z > 0.0f) ? z.z : 0.01f * z.z;
    z.w = (z.w > 0.0f) ? z.w : 0.01f * z.w;

    reinterpret_cast<float4*>(out + base)[lane] = z;
}

extern "C" void kernel_launch(void* const* d_in, const int* in_sizes, int n_in,
                              void* d_out, int out_size)
{
    const float* x = (const float*)d_in[0];
    const float* w = (const float*)d_in[1];   // (2, 257); row 0 used
    float* out = (float*)d_out;

    const int B = in_sizes[0] / D_LEN;        // 65536
    const int grid = (B + ROWS_PER_BLOCK - 1) / ROWS_PER_BLOCK;

    wavelet_fused_kernel<<<grid, THREADS>>>(x, w, out, B);
}